// round 5
// baseline (speedup 1.0000x reference)
#include <cuda_runtime.h>
#include <cuda_bf16.h>

// out[g, :] = sum over rows r with batch[r]==g of x[r, :]
// (softmax over a size-1 axis == 1.0 -> W, b mathematically dead).
// x: [N, 128] fp32, batch: [N] int32 SORTED, out: [10000, 128] fp32.
//
// Inputs identified BY ELEMENT COUNT (robust to metadata ordering):
//   x = unique largest (N*128), batch = unique with N elems.
//
// Each warp owns RPW=64 contiguous rows (grid ~1954 blocks -> ~1.9 waves,
// small tail fraction). Per 32-row tile: ONE coalesced id load; sorted =>
// single-segment iff first==last -> branch-free unroll-8 streaming
// accumulate (~73% of tiles). Boundary tiles distribute ids via shfl.
// Segment flushes via red.global.add.v4.f32 (out is L2-resident, 5 MB).

#define TX   32
#define TY   8
#define C    128
#define RPW  64                      // rows per warp
#define ROWS_PER_BLOCK (TY * RPW)    // 512

__device__ __forceinline__ void red_add_v4(float* addr, float4 v) {
    asm volatile("red.global.add.v4.f32 [%0], {%1, %2, %3, %4};"
                 :: "l"(addr), "f"(v.x), "f"(v.y), "f"(v.z), "f"(v.w)
                 : "memory");
}

__global__ void zero_out_kernel(float4* __restrict__ out, int n4) {
    int i = blockIdx.x * blockDim.x + threadIdx.x;
    if (i < n4) out[i] = make_float4(0.f, 0.f, 0.f, 0.f);
}

__global__ __launch_bounds__(TX * TY)
void segsum_kernel(const float4* __restrict__ x4,   // [N, 32] float4 view
                   const int* __restrict__ batch,   // [N] int32 sorted
                   float* __restrict__ out,         // [G, 128]
                   int N, int G) {
    const int lane = threadIdx.x;                   // column group
    int r0 = (blockIdx.x * TY + threadIdx.y) * RPW;
    if (r0 >= N) return;
    const int rend = min(r0 + RPW, N);

    float4 acc = make_float4(0.f, 0.f, 0.f, 0.f);
    int cur = __ldg(&batch[r0]);

    for (int t = r0; t < rend; t += 32) {
        const int m = rend - t < 32 ? rend - t : 32;
        // one coalesced id load per 32-row tile
        int id = __ldg(&batch[t + (lane < m ? lane : m - 1)]);
        const int first = __shfl_sync(0xffffffffu, id, 0);
        const int last  = __shfl_sync(0xffffffffu, id, 31);

        if (first == last && m == 32) {
            // whole tile in one segment (sorted): branch-free fast path
            if (first != cur) {
                int g = min(max(cur, 0), G - 1);
                red_add_v4(out + (size_t)g * C + lane * 4, acc);
                acc = make_float4(0.f, 0.f, 0.f, 0.f);
                cur = first;
            }
            const float4* p = x4 + (size_t)t * (C / 4) + lane;
            #pragma unroll 8
            for (int i = 0; i < 32; ++i) {
                float4 v = __ldcs(p + (size_t)i * (C / 4));
                acc.x += v.x; acc.y += v.y; acc.z += v.z; acc.w += v.w;
            }
        } else {
            // boundary tile: per-row ids via shfl (no extra gmem traffic)
            for (int i = 0; i < m; ++i) {
                int b = __shfl_sync(0xffffffffu, id, i);
                float4 v = __ldcs(&x4[(size_t)(t + i) * (C / 4) + lane]);
                if (b != cur) {
                    int g = min(max(cur, 0), G - 1);
                    red_add_v4(out + (size_t)g * C + lane * 4, acc);
                    acc = make_float4(0.f, 0.f, 0.f, 0.f);
                    cur = b;
                }
                acc.x += v.x; acc.y += v.y; acc.z += v.z; acc.w += v.w;
            }
        }
    }
    int g = min(max(cur, 0), G - 1);
    red_add_v4(out + (size_t)g * C + lane * 4, acc);
}

extern "C" void kernel_launch(void* const* d_in, const int* in_sizes, int n_in,
                              void* d_out, int out_size) {
    // identify inputs by element count
    int xi = 0;
    long long best = -1;
    for (int i = 0; i < n_in; ++i)
        if ((long long)in_sizes[i] > best) { best = in_sizes[i]; xi = i; }
    const int N = in_sizes[xi] / C;
    int bi = -1;
    for (int i = 0; i < n_in; ++i)
        if (i != xi && in_sizes[i] == N) { bi = i; break; }
    if (bi < 0) bi = (xi == 1) ? 0 : 1;

    const float* x     = (const float*)d_in[xi];
    const int*   batch = (const int*)d_in[bi];
    float* out = (float*)d_out;
    const int G = out_size / C;

    // zero the poisoned output (vectorized)
    int n4 = out_size / 4;
    zero_out_kernel<<<(n4 + 255) / 256, 256>>>((float4*)out, n4);

    dim3 block(TX, TY);
    int grid = (N + ROWS_PER_BLOCK - 1) / ROWS_PER_BLOCK;
    segsum_kernel<<<grid, block>>>((const float4*)x, batch, out, N, G);
}